// round 4
// baseline (speedup 1.0000x reference)
#include <cuda_runtime.h>
#include <cstdint>

// Problem constants (fixed for this problem instance)
#define INPUT_SZ 4
#define HID      2048
#define OUT_SZ   2
#define GD       8      // gaussian basis dim
#define NSUP     2
#define BATCH    32
#define SEQ      1000

#define TPB      256
#define CPT      8            // hidden units per thread (HID / TPB)
#define NPAIR    4            // CPT / 2 (float2 pairs)
#define NWARP    (TPB / 32)

// ---------- packed fp32x2 helpers (Blackwell FFMA2 path) ----------
__device__ __forceinline__ float2 ffma2(float2 a, float2 b, float2 c) {
    float2 d;
    asm("fma.rn.f32x2 %0, %1, %2, %3;"
        : "=l"(*reinterpret_cast<unsigned long long*>(&d))
        : "l"(*reinterpret_cast<unsigned long long*>(&a)),
          "l"(*reinterpret_cast<unsigned long long*>(&b)),
          "l"(*reinterpret_cast<unsigned long long*>(&c)));
    return d;
}
__device__ __forceinline__ float2 fmul2(float2 a, float2 b) {
    float2 d;
    asm("mul.rn.f32x2 %0, %1, %2;"
        : "=l"(*reinterpret_cast<unsigned long long*>(&d))
        : "l"(*reinterpret_cast<unsigned long long*>(&a)),
          "l"(*reinterpret_cast<unsigned long long*>(&b)));
    return d;
}
__device__ __forceinline__ float2 fadd2(float2 a, float2 b) {
    float2 d;
    asm("add.rn.f32x2 %0, %1, %2;"
        : "=l"(*reinterpret_cast<unsigned long long*>(&d))
        : "l"(*reinterpret_cast<unsigned long long*>(&a)),
          "l"(*reinterpret_cast<unsigned long long*>(&b)));
    return d;
}

// Accurate fast tanh: 2 MUFU (ex2 + rcp), rel err ~1e-7. Safe for 1e-3 harness tol.
__device__ __forceinline__ float ftanh(float x) {
    float e = __expf(-2.0f * fabsf(x));          // FMUL + MUFU.EX2
    float t = __fdividef(1.0f - e, 1.0f + e);    // 2 FADD + MUFU.RCP + FMUL
    return copysignf(t, x);
}

__global__ void __launch_bounds__(TPB, 1)
rnn_kernel(const float* __restrict__ input,   // (B, T, I)
           const float* __restrict__ noise,   // (B, T, H)
           const float* __restrict__ wi_w,    // (I, S, G)
           const float* __restrict__ m_w,     // (R, S, G)
           const float* __restrict__ n_w,     // (R, S, G)
           const float* __restrict__ wo_w,    // (O, S, G)
           const float* __restrict__ wi_b,    // (I, S)
           const float* __restrict__ m_b,     // (R, S)
           const float* __restrict__ n_b,     // (R, S)
           const float* __restrict__ h0_w,    // (S, G)
           const float* __restrict__ gb,      // (G, H)
           const float* __restrict__ sup,     // (S, H)
           float* __restrict__ out)           // (B, T, O)
{
    __shared__ float4 s_in[SEQ];          // whole per-batch input, staged once (16 KB)
    __shared__ float4 s_part[2][NWARP];   // double-buffered warp partials -> 1 bar/step

    const int tid  = threadIdx.x;
    const int b    = blockIdx.x;
    const int wid  = tid >> 5;
    const int lane = tid & 31;

    // stage input[b] into shared
    const float4* in4 = reinterpret_cast<const float4*>(input) + (size_t)b * SEQ;
    for (int i = tid; i < SEQ; i += TPB) s_in[i] = in4[i];

    // ---------------- per-unit proxy parameters (registers) ----------------
    // Folds: wi' = ALPHA*wi, m' = ALPHA*m; leak 0.8 and noise 0.05 as immediates.
    float2 hreg[NPAIR], rreg[NPAIR];
    float2 n0v[NPAIR], n1v[NPAIR], wo0v[NPAIR], wo1v[NPAIR], m0v[NPAIR], m1v[NPAIR];
    float2 wiv[INPUT_SZ][NPAIR];

    const int ubase = tid * CPT;
    for (int j = 0; j < NPAIR; ++j) {
        for (int half = 0; half < 2; ++half) {
            const int u = ubase + 2 * j + half;
            float gbv[GD];
            #pragma unroll
            for (int g = 0; g < GD; ++g) gbv[g] = gb[(size_t)g * HID + u];
            const float su0 = sup[u];
            const float su1 = sup[HID + u];

            auto mixp = [&](const float* w, const float* bias, int row) -> float {
                float a0 = bias ? bias[row * NSUP + 0] : 0.0f;
                float a1 = bias ? bias[row * NSUP + 1] : 0.0f;
                #pragma unroll
                for (int g = 0; g < GD; ++g) {
                    a0 = fmaf(w[(row * NSUP + 0) * GD + g], gbv[g], a0);
                    a1 = fmaf(w[(row * NSUP + 1) * GD + g], gbv[g], a1);
                }
                return a0 * su0 + a1 * su1;
            };

            reinterpret_cast<float*>(&wiv[0][j])[half] = 0.2f * mixp(wi_w, wi_b, 0);
            reinterpret_cast<float*>(&wiv[1][j])[half] = 0.2f * mixp(wi_w, wi_b, 1);
            reinterpret_cast<float*>(&wiv[2][j])[half] = 0.2f * mixp(wi_w, wi_b, 2);
            reinterpret_cast<float*>(&wiv[3][j])[half] = 0.2f * mixp(wi_w, wi_b, 3);
            reinterpret_cast<float*>(&m0v[j])[half]  = 0.2f * mixp(m_w, m_b, 0);
            reinterpret_cast<float*>(&m1v[j])[half]  = 0.2f * mixp(m_w, m_b, 1);
            reinterpret_cast<float*>(&n0v[j])[half]  = mixp(n_w, n_b, 0);
            reinterpret_cast<float*>(&n1v[j])[half]  = mixp(n_w, n_b, 1);
            reinterpret_cast<float*>(&wo0v[j])[half] = mixp(wo_w, nullptr, 0);
            reinterpret_cast<float*>(&wo1v[j])[half] = mixp(wo_w, nullptr, 1);

            // h0[u] = (h0_w[0,:]·gb)·sup0 + (h0_w[1,:]·gb)·sup1
            float a0 = 0.0f, a1 = 0.0f;
            #pragma unroll
            for (int g = 0; g < GD; ++g) {
                a0 = fmaf(h0_w[g],      gbv[g], a0);
                a1 = fmaf(h0_w[GD + g], gbv[g], a1);
            }
            const float h0u = a0 * su0 + a1 * su1;
            reinterpret_cast<float*>(&hreg[j])[half] = h0u;
            reinterpret_cast<float*>(&rreg[j])[half] = ftanh(h0u);
        }
    }
    __syncthreads();  // s_in ready

    // ---------------- main recurrence ----------------
    const float4* nz4 = reinterpret_cast<const float4*>(noise)
                        + (size_t)b * SEQ * (HID / 4) + tid * 2;
    // distance-2 noise prefetch
    float4 nA0 = nz4[0],   nA1 = nz4[1];
    float4 nB0 = nz4[512], nB1 = nz4[513];

    const float2 K08  = make_float2(0.8f, 0.8f);
    const float2 K005 = make_float2(0.05f, 0.05f);
    float2* out2 = reinterpret_cast<float2*>(out) + (size_t)b * SEQ;

    auto step = [&](int t, float4& nzl0, float4& nzl1) {
        // 4 merged dot products on current r: s0,s1 (recurrence), o0,o1 (output t-1)
        float2 a0 = make_float2(0.f, 0.f), a1 = a0, a2 = a0, a3 = a0;
        #pragma unroll
        for (int j = 0; j < NPAIR; ++j) {
            a0 = ffma2(rreg[j], n0v[j],  a0);
            a1 = ffma2(rreg[j], n1v[j],  a1);
            a2 = ffma2(rreg[j], wo0v[j], a2);
            a3 = ffma2(rreg[j], wo1v[j], a3);
        }
        float p0 = a0.x + a0.y, p1 = a1.x + a1.y, p2 = a2.x + a2.y, p3 = a3.x + a3.y;
        #pragma unroll
        for (int off = 16; off > 0; off >>= 1) {
            p0 += __shfl_xor_sync(0xffffffffu, p0, off);
            p1 += __shfl_xor_sync(0xffffffffu, p1, off);
            p2 += __shfl_xor_sync(0xffffffffu, p2, off);
            p3 += __shfl_xor_sync(0xffffffffu, p3, off);
        }
        const int buf = t & 1;
        if (lane == 0) s_part[buf][wid] = make_float4(p0, p1, p2, p3);

        // s-independent work overlapped with the reduce: leak + noise + input proj
        const float4 inv = s_in[t];
        const float2 ix = make_float2(inv.x, inv.x);
        const float2 iy = make_float2(inv.y, inv.y);
        const float2 iz = make_float2(inv.z, inv.z);
        const float2 iw = make_float2(inv.w, inv.w);
        float2 nzf[NPAIR];
        nzf[0] = make_float2(nzl0.x, nzl0.y);
        nzf[1] = make_float2(nzl0.z, nzl0.w);
        nzf[2] = make_float2(nzl1.x, nzl1.y);
        nzf[3] = make_float2(nzl1.z, nzl1.w);
        float2 tac[NPAIR];
        #pragma unroll
        for (int j = 0; j < NPAIR; ++j) {
            float2 tmp = fmul2(ix, wiv[0][j]);
            tmp = ffma2(iy, wiv[1][j], tmp);
            tmp = ffma2(iz, wiv[2][j], tmp);
            tmp = ffma2(iw, wiv[3][j], tmp);
            tmp = ffma2(K005, nzf[j], tmp);
            tmp = ffma2(K08, hreg[j], tmp);
            tac[j] = tmp;
        }
        // prefetch noise for t+2 (clamped near the end; value unused then)
        const int tn = (t + 2 < SEQ) ? (t + 2) : t;
        nzl0 = nz4[(size_t)tn * 512];
        nzl1 = nz4[(size_t)tn * 512 + 1];

        __syncthreads();
        const float2* pp = reinterpret_cast<const float2*>(&s_part[buf][0]);
        float2 sv = make_float2(0.f, 0.f);
        #pragma unroll
        for (int w = 0; w < NWARP; ++w) sv = fadd2(sv, pp[2 * w]);

        if (t > 0 && tid == 0) {
            float2 ov = make_float2(0.f, 0.f);
            #pragma unroll
            for (int w = 0; w < NWARP; ++w) ov = fadd2(ov, pp[2 * w + 1]);
            out2[t - 1] = ov;   // output for r_{t-1}
        }

        const float2 s0v = make_float2(sv.x, sv.x);
        const float2 s1v = make_float2(sv.y, sv.y);
        #pragma unroll
        for (int j = 0; j < NPAIR; ++j) {
            const float2 hn = ffma2(s0v, m0v[j], ffma2(s1v, m1v[j], tac[j]));
            hreg[j] = hn;
            rreg[j].x = ftanh(hn.x);
            rreg[j].y = ftanh(hn.y);
        }
    };

    #pragma unroll 1
    for (int t = 0; t < SEQ; t += 2) {
        step(t,     nA0, nA1);
        step(t + 1, nB0, nB1);
    }

    // ---------------- epilogue: output for t = SEQ-1 ----------------
    {
        float2 a2 = make_float2(0.f, 0.f), a3 = a2;
        #pragma unroll
        for (int j = 0; j < NPAIR; ++j) {
            a2 = ffma2(rreg[j], wo0v[j], a2);
            a3 = ffma2(rreg[j], wo1v[j], a3);
        }
        float p2 = a2.x + a2.y, p3 = a3.x + a3.y;
        #pragma unroll
        for (int off = 16; off > 0; off >>= 1) {
            p2 += __shfl_xor_sync(0xffffffffu, p2, off);
            p3 += __shfl_xor_sync(0xffffffffu, p3, off);
        }
        if (lane == 0) s_part[0][wid] = make_float4(p2, p3, 0.f, 0.f);
        __syncthreads();
        if (tid == 0) {
            float2 ov = make_float2(0.f, 0.f);
            #pragma unroll
            for (int w = 0; w < NWARP; ++w) {
                const float4 q = s_part[0][w];
                ov.x += q.x;
                ov.y += q.y;
            }
            out2[SEQ - 1] = ov;
        }
    }
}

extern "C" void kernel_launch(void* const* d_in, const int* in_sizes, int n_in,
                              void* d_out, int out_size) {
    (void)in_sizes; (void)n_in; (void)out_size;
    rnn_kernel<<<BATCH, TPB>>>(
        (const float*)d_in[0],   // input
        (const float*)d_in[1],   // noise
        (const float*)d_in[2],   // wi_weights
        (const float*)d_in[3],   // m_weights
        (const float*)d_in[4],   // n_weights
        (const float*)d_in[5],   // wo_weights
        (const float*)d_in[6],   // wi_biases
        (const float*)d_in[7],   // m_biases
        (const float*)d_in[8],   // n_biases
        (const float*)d_in[9],   // h0_weights
        (const float*)d_in[10],  // gaussian_basis
        (const float*)d_in[11],  // supports
        (float*)d_out);
}

// round 6
// speedup vs baseline: 1.1867x; 1.1867x over previous
#include <cuda_runtime.h>
#include <cstdint>

// Problem constants (fixed for this problem instance)
#define INPUT_SZ 4
#define HID      2048
#define OUT_SZ   2
#define GD       8      // gaussian basis dim
#define NSUP     2
#define BATCH    32
#define SEQ      1000

#define TPB      512
#define CPT      4            // hidden units per thread (HID / TPB)
#define NPAIR    2            // CPT / 2 (float2 pairs)
#define NWARP    (TPB / 32)   // 16

// ---------- packed fp32x2 helpers (Blackwell FFMA2 path) ----------
__device__ __forceinline__ float2 ffma2(float2 a, float2 b, float2 c) {
    float2 d;
    asm("fma.rn.f32x2 %0, %1, %2, %3;"
        : "=l"(*reinterpret_cast<unsigned long long*>(&d))
        : "l"(*reinterpret_cast<unsigned long long*>(&a)),
          "l"(*reinterpret_cast<unsigned long long*>(&b)),
          "l"(*reinterpret_cast<unsigned long long*>(&c)));
    return d;
}
__device__ __forceinline__ float2 fmul2(float2 a, float2 b) {
    float2 d;
    asm("mul.rn.f32x2 %0, %1, %2;"
        : "=l"(*reinterpret_cast<unsigned long long*>(&d))
        : "l"(*reinterpret_cast<unsigned long long*>(&a)),
          "l"(*reinterpret_cast<unsigned long long*>(&b)));
    return d;
}

__device__ __forceinline__ float frcp(float x) {
    float r;
    asm("rcp.approx.f32 %0, %1;" : "=f"(r) : "f"(x));
    return r;
}

// Exact-enough tanh, branch-free, 3 FMA-class + 2 MUFU:
// tanh(x) = 1 - 2/(e^{2x}+1).  x->+inf: e=inf -> rcp=0 -> 1; x->-inf: e=0 -> -1.
__device__ __forceinline__ float ftanh(float x) {
    float e = __expf(2.0f * x);       // FMUL + MUFU.EX2
    float r = frcp(e + 1.0f);         // FADD + MUFU.RCP
    return fmaf(-2.0f, r, 1.0f);      // FFMA
}

__global__ void __launch_bounds__(TPB, 1)
rnn_kernel(const float* __restrict__ input,   // (B, T, I)
           const float* __restrict__ noise,   // (B, T, H)
           const float* __restrict__ wi_w,    // (I, S, G)
           const float* __restrict__ m_w,     // (R, S, G)
           const float* __restrict__ n_w,     // (R, S, G)
           const float* __restrict__ wo_w,    // (O, S, G)
           const float* __restrict__ wi_b,    // (I, S)
           const float* __restrict__ m_b,     // (R, S)
           const float* __restrict__ n_b,     // (R, S)
           const float* __restrict__ h0_w,    // (S, G)
           const float* __restrict__ gb,      // (G, H)
           const float* __restrict__ sup,     // (S, H)
           float* __restrict__ out)           // (B, T, O)
{
    __shared__ float4 s_in[SEQ];          // whole per-batch input, staged once (16 KB)
    __shared__ float4 s_part[2][NWARP];   // double-buffered warp partials -> 1 bar/step

    const int tid  = threadIdx.x;
    const int b    = blockIdx.x;
    const int wid  = tid >> 5;
    const int lane = tid & 31;

    // stage input[b] into shared
    const float4* in4 = reinterpret_cast<const float4*>(input) + (size_t)b * SEQ;
    for (int i = tid; i < SEQ; i += TPB) s_in[i] = in4[i];

    // ---------------- per-unit proxy parameters (registers) ----------------
    // Folds: wi' = ALPHA*wi, m' = ALPHA*m; leak 0.8 and noise 0.05 as immediates.
    float2 hreg[NPAIR], rreg[NPAIR];
    float2 n0v[NPAIR], n1v[NPAIR], wo0v[NPAIR], wo1v[NPAIR], m0v[NPAIR], m1v[NPAIR];
    float2 wiv[INPUT_SZ][NPAIR];

    const int ubase = tid * CPT;
    for (int j = 0; j < NPAIR; ++j) {
        for (int half = 0; half < 2; ++half) {
            const int u = ubase + 2 * j + half;
            float gbv[GD];
            #pragma unroll
            for (int g = 0; g < GD; ++g) gbv[g] = gb[(size_t)g * HID + u];
            const float su0 = sup[u];
            const float su1 = sup[HID + u];

            auto mixp = [&](const float* w, const float* bias, int row) -> float {
                float a0 = bias ? bias[row * NSUP + 0] : 0.0f;
                float a1 = bias ? bias[row * NSUP + 1] : 0.0f;
                #pragma unroll
                for (int g = 0; g < GD; ++g) {
                    a0 = fmaf(w[(row * NSUP + 0) * GD + g], gbv[g], a0);
                    a1 = fmaf(w[(row * NSUP + 1) * GD + g], gbv[g], a1);
                }
                return a0 * su0 + a1 * su1;
            };

            reinterpret_cast<float*>(&wiv[0][j])[half] = 0.2f * mixp(wi_w, wi_b, 0);
            reinterpret_cast<float*>(&wiv[1][j])[half] = 0.2f * mixp(wi_w, wi_b, 1);
            reinterpret_cast<float*>(&wiv[2][j])[half] = 0.2f * mixp(wi_w, wi_b, 2);
            reinterpret_cast<float*>(&wiv[3][j])[half] = 0.2f * mixp(wi_w, wi_b, 3);
            reinterpret_cast<float*>(&m0v[j])[half]  = 0.2f * mixp(m_w, m_b, 0);
            reinterpret_cast<float*>(&m1v[j])[half]  = 0.2f * mixp(m_w, m_b, 1);
            reinterpret_cast<float*>(&n0v[j])[half]  = mixp(n_w, n_b, 0);
            reinterpret_cast<float*>(&n1v[j])[half]  = mixp(n_w, n_b, 1);
            reinterpret_cast<float*>(&wo0v[j])[half] = mixp(wo_w, nullptr, 0);
            reinterpret_cast<float*>(&wo1v[j])[half] = mixp(wo_w, nullptr, 1);

            // h0[u] = (h0_w[0,:]·gb)·sup0 + (h0_w[1,:]·gb)·sup1
            float a0 = 0.0f, a1 = 0.0f;
            #pragma unroll
            for (int g = 0; g < GD; ++g) {
                a0 = fmaf(h0_w[g],      gbv[g], a0);
                a1 = fmaf(h0_w[GD + g], gbv[g], a1);
            }
            const float h0u = a0 * su0 + a1 * su1;
            reinterpret_cast<float*>(&hreg[j])[half] = h0u;
            reinterpret_cast<float*>(&rreg[j])[half] = ftanh(h0u);
        }
    }
    __syncthreads();  // s_in ready

    // ---------------- main recurrence ----------------
    // Each thread owns units [tid*4, tid*4+4) -> exactly one float4 of noise per step.
    const float4* nz4 = reinterpret_cast<const float4*>(noise)
                        + (size_t)b * SEQ * (HID / 4) + tid;
    // distance-2 noise prefetch (streaming loads: read-once data)
    float4 nA = __ldcs(&nz4[0]);
    float4 nB = __ldcs(&nz4[HID / 4]);

    const float2 K08  = make_float2(0.8f, 0.8f);
    const float2 K005 = make_float2(0.05f, 0.05f);
    float2* out2 = reinterpret_cast<float2*>(out) + (size_t)b * SEQ;

    auto step = [&](int t, float4& nzl) {
        // 4 merged dot products on current r: s0,s1 (recurrence), o0,o1 (output t-1)
        float2 a0 = make_float2(0.f, 0.f), a1 = a0, a2 = a0, a3 = a0;
        #pragma unroll
        for (int j = 0; j < NPAIR; ++j) {
            a0 = ffma2(rreg[j], n0v[j],  a0);
            a1 = ffma2(rreg[j], n1v[j],  a1);
            a2 = ffma2(rreg[j], wo0v[j], a2);
            a3 = ffma2(rreg[j], wo1v[j], a3);
        }
        float p0 = a0.x + a0.y, p1 = a1.x + a1.y, p2 = a2.x + a2.y, p3 = a3.x + a3.y;
        #pragma unroll
        for (int off = 16; off > 0; off >>= 1) {
            p0 += __shfl_xor_sync(0xffffffffu, p0, off);
            p1 += __shfl_xor_sync(0xffffffffu, p1, off);
            p2 += __shfl_xor_sync(0xffffffffu, p2, off);
            p3 += __shfl_xor_sync(0xffffffffu, p3, off);
        }
        const int buf = t & 1;
        if (lane == 0) s_part[buf][wid] = make_float4(p0, p1, p2, p3);

        // s-independent work overlapped with the reduce: leak + noise + input proj
        const float4 inv = s_in[t];
        const float2 ix = make_float2(inv.x, inv.x);
        const float2 iy = make_float2(inv.y, inv.y);
        const float2 iz = make_float2(inv.z, inv.z);
        const float2 iw = make_float2(inv.w, inv.w);
        float2 nzf[NPAIR];
        nzf[0] = make_float2(nzl.x, nzl.y);
        nzf[1] = make_float2(nzl.z, nzl.w);
        float2 tac[NPAIR];
        #pragma unroll
        for (int j = 0; j < NPAIR; ++j) {
            float2 tmp = fmul2(ix, wiv[0][j]);
            tmp = ffma2(iy, wiv[1][j], tmp);
            tmp = ffma2(iz, wiv[2][j], tmp);
            tmp = ffma2(iw, wiv[3][j], tmp);
            tmp = ffma2(K005, nzf[j], tmp);
            tmp = ffma2(K08, hreg[j], tmp);
            tac[j] = tmp;
        }
        // prefetch noise for t+2 (branchless clamp; value unused at the tail)
        const int tn = min(t + 2, SEQ - 1);
        nzl = __ldcs(&nz4[(size_t)tn * (HID / 4)]);

        __syncthreads();
        // Cross-warp combine: all 32 lanes load one of the 16 partials (pairs of
        // lanes share an address -> LDS broadcast, conflict-free), then a 4-level
        // butterfly over each 16-lane half yields the full sum in EVERY lane.
        float4 q = s_part[buf][lane & (NWARP - 1)];
        float s0 = q.x, s1 = q.y;
        #pragma unroll
        for (int off = 8; off > 0; off >>= 1) {
            s0 += __shfl_xor_sync(0xffffffffu, s0, off);
            s1 += __shfl_xor_sync(0xffffffffu, s1, off);
        }
        if (wid == 0) {
            float o0 = q.z, o1 = q.w;
            #pragma unroll
            for (int off = 8; off > 0; off >>= 1) {
                o0 += __shfl_xor_sync(0xffffffffu, o0, off);
                o1 += __shfl_xor_sync(0xffffffffu, o1, off);
            }
            if (lane == 0 && t > 0) out2[t - 1] = make_float2(o0, o1);
        }

        const float2 s0v = make_float2(s0, s0);
        const float2 s1v = make_float2(s1, s1);
        #pragma unroll
        for (int j = 0; j < NPAIR; ++j) {
            const float2 hn = ffma2(s0v, m0v[j], ffma2(s1v, m1v[j], tac[j]));
            hreg[j] = hn;
            rreg[j].x = ftanh(hn.x);
            rreg[j].y = ftanh(hn.y);
        }
    };

    #pragma unroll 1
    for (int t = 0; t < SEQ; t += 2) {
        step(t,     nA);
        step(t + 1, nB);
    }

    // ---------------- epilogue: output for t = SEQ-1 ----------------
    {
        float2 a2 = make_float2(0.f, 0.f), a3 = a2;
        #pragma unroll
        for (int j = 0; j < NPAIR; ++j) {
            a2 = ffma2(rreg[j], wo0v[j], a2);
            a3 = ffma2(rreg[j], wo1v[j], a3);
        }
        float p2 = a2.x + a2.y, p3 = a3.x + a3.y;
        #pragma unroll
        for (int off = 16; off > 0; off >>= 1) {
            p2 += __shfl_xor_sync(0xffffffffu, p2, off);
            p3 += __shfl_xor_sync(0xffffffffu, p3, off);
        }
        if (lane == 0) s_part[0][wid] = make_float4(p2, p3, 0.f, 0.f);
        __syncthreads();
        if (wid == 0) {
            float4 q = s_part[0][lane & (NWARP - 1)];
            float o0 = q.x, o1 = q.y;
            #pragma unroll
            for (int off = 8; off > 0; off >>= 1) {
                o0 += __shfl_xor_sync(0xffffffffu, o0, off);
                o1 += __shfl_xor_sync(0xffffffffu, o1, off);
            }
            if (lane == 0) out2[SEQ - 1] = make_float2(o0, o1);
        }
    }
}

extern "C" void kernel_launch(void* const* d_in, const int* in_sizes, int n_in,
                              void* d_out, int out_size) {
    (void)in_sizes; (void)n_in; (void)out_size;
    rnn_kernel<<<BATCH, TPB>>>(
        (const float*)d_in[0],   // input
        (const float*)d_in[1],   // noise
        (const float*)d_in[2],   // wi_weights
        (const float*)d_in[3],   // m_weights
        (const float*)d_in[4],   // n_weights
        (const float*)d_in[5],   // wo_weights
        (const float*)d_in[6],   // wi_biases
        (const float*)d_in[7],   // m_biases
        (const float*)d_in[8],   // n_biases
        (const float*)d_in[9],   // h0_weights
        (const float*)d_in[10],  // gaussian_basis
        (const float*)d_in[11],  // supports
        (float*)d_out);
}

// round 7
// speedup vs baseline: 1.1892x; 1.0021x over previous
#include <cuda_runtime.h>
#include <cstdint>

// Problem constants (fixed for this problem instance)
#define INPUT_SZ 4
#define HID      2048
#define OUT_SZ   2
#define GD       8      // gaussian basis dim
#define NSUP     2
#define BATCH    32
#define SEQ      1000

#define TPB      256
#define CPT      8            // hidden units per thread (HID / TPB)
#define NPAIR    4            // CPT / 2 (float2 pairs)
#define NWARP    (TPB / 32)   // 8

// 262 MB fp32 scratch for all r states  (allowed: static __device__ array)
__device__ float4 g_r[(size_t)BATCH * SEQ * (HID / 4)];
// Precomputed output weights: g_wo[h] = (wo0[h], wo1[h])
__device__ float2 g_wo[HID];

// ---------- packed fp32x2 helpers ----------
__device__ __forceinline__ float2 ffma2(float2 a, float2 b, float2 c) {
    float2 d;
    asm("fma.rn.f32x2 %0, %1, %2, %3;"
        : "=l"(*reinterpret_cast<unsigned long long*>(&d))
        : "l"(*reinterpret_cast<unsigned long long*>(&a)),
          "l"(*reinterpret_cast<unsigned long long*>(&b)),
          "l"(*reinterpret_cast<unsigned long long*>(&c)));
    return d;
}
__device__ __forceinline__ float2 fmul2(float2 a, float2 b) {
    float2 d;
    asm("mul.rn.f32x2 %0, %1, %2;"
        : "=l"(*reinterpret_cast<unsigned long long*>(&d))
        : "l"(*reinterpret_cast<unsigned long long*>(&a)),
          "l"(*reinterpret_cast<unsigned long long*>(&b)));
    return d;
}
__device__ __forceinline__ float2 fadd2(float2 a, float2 b) {
    float2 d;
    asm("add.rn.f32x2 %0, %1, %2;"
        : "=l"(*reinterpret_cast<unsigned long long*>(&d))
        : "l"(*reinterpret_cast<unsigned long long*>(&a)),
          "l"(*reinterpret_cast<unsigned long long*>(&b)));
    return d;
}
__device__ __forceinline__ float4 fadd4(float4 a, float4 b) {
    float4 r;
    r.x = a.x + b.x; r.y = a.y + b.y; r.z = a.z + b.z; r.w = a.w + b.w;
    return r;
}

__device__ __forceinline__ float fex2(float x) {
    float r; asm("ex2.approx.f32 %0, %1;" : "=f"(r) : "f"(x)); return r;
}
__device__ __forceinline__ float frcp(float x) {
    float r; asm("rcp.approx.f32 %0, %1;" : "=f"(r) : "f"(x)); return r;
}
// Exact-enough tanh: 1 FMUL + EX2 + FADD + RCP + FFMA  (rel err ~1e-7)
// tanh(x) = 1 - 2/(e^{2x}+1);  2x*log2(e) folded into one multiply.
__device__ __forceinline__ float ftanh(float x) {
    float e = fex2(x * 2.885390081777927f);   // e^{2x}
    float r = frcp(e + 1.0f);
    return fmaf(-2.0f, r, 1.0f);
}

// ---- shared proxy-parameter mixer (per hidden unit u, weight row `row`) ----
__device__ __forceinline__ float mix_unit(const float* __restrict__ w,
                                          const float* __restrict__ bias,
                                          int row, const float* gbv,
                                          float su0, float su1) {
    float a0 = bias ? bias[row * NSUP + 0] : 0.0f;
    float a1 = bias ? bias[row * NSUP + 1] : 0.0f;
    #pragma unroll
    for (int g = 0; g < GD; ++g) {
        a0 = fmaf(w[(row * NSUP + 0) * GD + g], gbv[g], a0);
        a1 = fmaf(w[(row * NSUP + 1) * GD + g], gbv[g], a1);
    }
    return a0 * su0 + a1 * su1;
}

// ================= kernel0: precompute wo (one-time, tiny) =================
__global__ void wo_kernel(const float* __restrict__ wo_w,
                          const float* __restrict__ gb,
                          const float* __restrict__ sup) {
    const int u = blockIdx.x * blockDim.x + threadIdx.x;
    if (u >= HID) return;
    float gbv[GD];
    #pragma unroll
    for (int g = 0; g < GD; ++g) gbv[g] = gb[(size_t)g * HID + u];
    const float su0 = sup[u], su1 = sup[HID + u];
    g_wo[u] = make_float2(mix_unit(wo_w, nullptr, 0, gbv, su0, su1),
                          mix_unit(wo_w, nullptr, 1, gbv, su0, su1));
}

// ================= kernel1: the recurrence (one CTA per batch) =============
__global__ void __launch_bounds__(TPB, 1)
rnn_kernel(const float* __restrict__ input,   // (B, T, I)
           const float* __restrict__ noise,   // (B, T, H)
           const float* __restrict__ wi_w,    // (I, S, G)
           const float* __restrict__ m_w,     // (R, S, G)
           const float* __restrict__ n_w,     // (R, S, G)
           const float* __restrict__ wi_b,    // (I, S)
           const float* __restrict__ m_b,     // (R, S)
           const float* __restrict__ n_b,     // (R, S)
           const float* __restrict__ h0_w,    // (S, G)
           const float* __restrict__ gb,      // (G, H)
           const float* __restrict__ sup)     // (S, H)
{
    __shared__ float4 s_in[SEQ];          // whole per-batch input, staged once (16 KB)
    __shared__ float2 s_part[2][NWARP];   // double-buffered warp partials -> 1 bar/step

    const int tid  = threadIdx.x;
    const int b    = blockIdx.x;
    const int wid  = tid >> 5;
    const int lane = tid & 31;

    // stage input[b] into shared
    const float4* in4 = reinterpret_cast<const float4*>(input) + (size_t)b * SEQ;
    for (int i = tid; i < SEQ; i += TPB) s_in[i] = in4[i];

    // ---------------- per-unit proxy parameters (registers) ----------------
    // Folds: wi' = ALPHA*wi, m' = ALPHA*m; leak 0.8 and noise 0.05 as immediates.
    float2 hreg[NPAIR], rreg[NPAIR];
    float2 n0v[NPAIR], n1v[NPAIR], m0v[NPAIR], m1v[NPAIR];
    float2 wiv[INPUT_SZ][NPAIR];

    const int ubase = tid * CPT;
    for (int j = 0; j < NPAIR; ++j) {
        for (int half = 0; half < 2; ++half) {
            const int u = ubase + 2 * j + half;
            float gbv[GD];
            #pragma unroll
            for (int g = 0; g < GD; ++g) gbv[g] = gb[(size_t)g * HID + u];
            const float su0 = sup[u];
            const float su1 = sup[HID + u];

            reinterpret_cast<float*>(&wiv[0][j])[half] = 0.2f * mix_unit(wi_w, wi_b, 0, gbv, su0, su1);
            reinterpret_cast<float*>(&wiv[1][j])[half] = 0.2f * mix_unit(wi_w, wi_b, 1, gbv, su0, su1);
            reinterpret_cast<float*>(&wiv[2][j])[half] = 0.2f * mix_unit(wi_w, wi_b, 2, gbv, su0, su1);
            reinterpret_cast<float*>(&wiv[3][j])[half] = 0.2f * mix_unit(wi_w, wi_b, 3, gbv, su0, su1);
            reinterpret_cast<float*>(&m0v[j])[half]  = 0.2f * mix_unit(m_w, m_b, 0, gbv, su0, su1);
            reinterpret_cast<float*>(&m1v[j])[half]  = 0.2f * mix_unit(m_w, m_b, 1, gbv, su0, su1);
            reinterpret_cast<float*>(&n0v[j])[half]  = mix_unit(n_w, n_b, 0, gbv, su0, su1);
            reinterpret_cast<float*>(&n1v[j])[half]  = mix_unit(n_w, n_b, 1, gbv, su0, su1);

            float a0 = 0.0f, a1 = 0.0f;
            #pragma unroll
            for (int g = 0; g < GD; ++g) {
                a0 = fmaf(h0_w[g],      gbv[g], a0);
                a1 = fmaf(h0_w[GD + g], gbv[g], a1);
            }
            const float h0u = a0 * su0 + a1 * su1;
            reinterpret_cast<float*>(&hreg[j])[half] = h0u;
            reinterpret_cast<float*>(&rreg[j])[half] = ftanh(h0u);
        }
    }
    __syncthreads();  // s_in ready

    // ---------------- main recurrence ----------------
    // thread owns units [tid*8, tid*8+8) -> two float4 of noise / r per step
    const float4* nz4 = reinterpret_cast<const float4*>(noise)
                        + (size_t)b * SEQ * (HID / 4) + tid * 2;
    float4* rout = g_r + (size_t)b * SEQ * (HID / 4) + tid * 2;

    // distance-2 noise prefetch (streaming: read-once)
    float4 nA0 = __ldcs(&nz4[0]),                nA1 = __ldcs(&nz4[1]);
    float4 nB0 = __ldcs(&nz4[HID / 4]),          nB1 = __ldcs(&nz4[HID / 4 + 1]);

    const float2 K08  = make_float2(0.8f, 0.8f);
    const float2 K005 = make_float2(0.05f, 0.05f);

    auto step = [&](int t, float4& z0, float4& z1) {
        // rank-2 dot on current r
        float2 a0 = make_float2(0.f, 0.f), a1 = a0;
        #pragma unroll
        for (int j = 0; j < NPAIR; ++j) {
            a0 = ffma2(rreg[j], n0v[j], a0);
            a1 = ffma2(rreg[j], n1v[j], a1);
        }
        float p0 = a0.x + a0.y, p1 = a1.x + a1.y;
        #pragma unroll
        for (int off = 16; off > 0; off >>= 1) {
            p0 += __shfl_xor_sync(0xffffffffu, p0, off);
            p1 += __shfl_xor_sync(0xffffffffu, p1, off);
        }
        const int buf = t & 1;
        if (lane == 0) s_part[buf][wid] = make_float2(p0, p1);

        // s-independent work overlapped with the reduce
        const float4 inv = s_in[t];
        const float2 ix = make_float2(inv.x, inv.x);
        const float2 iy = make_float2(inv.y, inv.y);
        const float2 iz = make_float2(inv.z, inv.z);
        const float2 iw = make_float2(inv.w, inv.w);
        float2 nzf[NPAIR];
        nzf[0] = make_float2(z0.x, z0.y);
        nzf[1] = make_float2(z0.z, z0.w);
        nzf[2] = make_float2(z1.x, z1.y);
        nzf[3] = make_float2(z1.z, z1.w);
        float2 tac[NPAIR];
        #pragma unroll
        for (int j = 0; j < NPAIR; ++j) {
            float2 tmp = fmul2(ix, wiv[0][j]);
            tmp = ffma2(iy, wiv[1][j], tmp);
            tmp = ffma2(iz, wiv[2][j], tmp);
            tmp = ffma2(iw, wiv[3][j], tmp);
            tmp = ffma2(K005, nzf[j], tmp);
            tmp = ffma2(K08, hreg[j], tmp);
            tac[j] = tmp;
        }
        // prefetch noise for t+2 (branchless clamp; unused at the tail)
        const int tn = min(t + 2, SEQ - 1);
        z0 = __ldcs(&nz4[(size_t)tn * (HID / 4)]);
        z1 = __ldcs(&nz4[(size_t)tn * (HID / 4) + 1]);

        __syncthreads();
        // Cross-warp combine: 8 float2 partials = 4 float4, LDS-broadcast + reg tree
        const float4* pp = reinterpret_cast<const float4*>(&s_part[buf][0]);
        const float4 u01 = fadd4(pp[0], pp[1]);
        const float4 u23 = fadd4(pp[2], pp[3]);
        const float4 uu  = fadd4(u01, u23);
        const float2 sv  = fadd2(make_float2(uu.x, uu.y), make_float2(uu.z, uu.w));

        const float2 s0v = make_float2(sv.x, sv.x);
        const float2 s1v = make_float2(sv.y, sv.y);
        #pragma unroll
        for (int j = 0; j < NPAIR; ++j) {
            const float2 hn = ffma2(s0v, m0v[j], ffma2(s1v, m1v[j], tac[j]));
            hreg[j] = hn;
            rreg[j].x = ftanh(hn.x);
            rreg[j].y = ftanh(hn.y);
        }
        // store r_t for the deferred output projection (fire-and-forget)
        float4* rt = rout + (size_t)t * (HID / 4);
        rt[0] = make_float4(rreg[0].x, rreg[0].y, rreg[1].x, rreg[1].y);
        rt[1] = make_float4(rreg[2].x, rreg[2].y, rreg[3].x, rreg[3].y);
    };

    #pragma unroll 1
    for (int t = 0; t < SEQ; t += 2) {
        step(t,     nA0, nA1);
        step(t + 1, nB0, nB1);
    }
}

// ================= kernel2: deferred output projection =====================
// grid (BATCH, SEQ/8), block 256: warp w handles t = blockIdx.y*8 + w.
__global__ void __launch_bounds__(256, 4)
out_kernel(float* __restrict__ out) {
    const int b    = blockIdx.x;
    const int wid  = threadIdx.x >> 5;
    const int lane = threadIdx.x & 31;
    const int t    = blockIdx.y * 8 + wid;

    const float4* rr = g_r + ((size_t)b * SEQ + t) * (HID / 4);
    const float4* wv = reinterpret_cast<const float4*>(g_wo);

    float o0 = 0.f, o1 = 0.f;
    #pragma unroll
    for (int k = 0; k < 16; ++k) {
        const float4 rv = __ldcs(&rr[k * 32 + lane]);          // h = k*128 + lane*4
        const float4 wa = __ldg(&wv[k * 64 + lane * 2]);       // (wo0,wo1) for h, h+1
        const float4 wb = __ldg(&wv[k * 64 + lane * 2 + 1]);   // (wo0,wo1) for h+2, h+3
        o0 = fmaf(rv.x, wa.x, fmaf(rv.y, wa.z, fmaf(rv.z, wb.x, fmaf(rv.w, wb.z, o0))));
        o1 = fmaf(rv.x, wa.y, fmaf(rv.y, wa.w, fmaf(rv.z, wb.y, fmaf(rv.w, wb.w, o1))));
    }
    #pragma unroll
    for (int off = 16; off > 0; off >>= 1) {
        o0 += __shfl_xor_sync(0xffffffffu, o0, off);
        o1 += __shfl_xor_sync(0xffffffffu, o1, off);
    }
    if (lane == 0)
        reinterpret_cast<float2*>(out)[(size_t)b * SEQ + t] = make_float2(o0, o1);
}

extern "C" void kernel_launch(void* const* d_in, const int* in_sizes, int n_in,
                              void* d_out, int out_size) {
    (void)in_sizes; (void)n_in; (void)out_size;
    const float* input = (const float*)d_in[0];
    const float* noise = (const float*)d_in[1];
    const float* wi_w  = (const float*)d_in[2];
    const float* m_w   = (const float*)d_in[3];
    const float* n_w   = (const float*)d_in[4];
    const float* wo_w  = (const float*)d_in[5];
    const float* wi_b  = (const float*)d_in[6];
    const float* m_b   = (const float*)d_in[7];
    const float* n_b   = (const float*)d_in[8];
    const float* h0_w  = (const float*)d_in[9];
    const float* gb    = (const float*)d_in[10];
    const float* sup   = (const float*)d_in[11];

    wo_kernel<<<HID / 256, 256>>>(wo_w, gb, sup);
    rnn_kernel<<<BATCH, TPB>>>(input, noise, wi_w, m_w, n_w,
                               wi_b, m_b, n_b, h0_w, gb, sup);
    out_kernel<<<dim3(BATCH, SEQ / 8), 256>>>((float*)d_out);
}

// round 8
// speedup vs baseline: 1.4631x; 1.2303x over previous
#include <cuda_runtime.h>
#include <cstdint>

// Problem constants (fixed for this problem instance)
#define INPUT_SZ 4
#define HID      2048
#define OUT_SZ   2
#define GD       8      // gaussian basis dim
#define NSUP     2
#define BATCH    32
#define SEQ      1000

#define TPB      512
#define CPT      4            // hidden units per thread (HID / TPB)
#define NPAIR    2            // CPT / 2 (float2 pairs)
#define NWARP    (TPB / 32)   // 16

// 262 MB fp32 scratch for all r states (static __device__ array: allowed)
__device__ float4 g_r[(size_t)BATCH * SEQ * (HID / 4)];
// Precomputed output weights: g_wo[h] = (wo0[h], wo1[h])
__device__ float2 g_wo[HID];

// ---------- packed fp32x2 helpers ----------
__device__ __forceinline__ float2 ffma2(float2 a, float2 b, float2 c) {
    float2 d;
    asm("fma.rn.f32x2 %0, %1, %2, %3;"
        : "=l"(*reinterpret_cast<unsigned long long*>(&d))
        : "l"(*reinterpret_cast<unsigned long long*>(&a)),
          "l"(*reinterpret_cast<unsigned long long*>(&b)),
          "l"(*reinterpret_cast<unsigned long long*>(&c)));
    return d;
}
__device__ __forceinline__ float2 fmul2(float2 a, float2 b) {
    float2 d;
    asm("mul.rn.f32x2 %0, %1, %2;"
        : "=l"(*reinterpret_cast<unsigned long long*>(&d))
        : "l"(*reinterpret_cast<unsigned long long*>(&a)),
          "l"(*reinterpret_cast<unsigned long long*>(&b)));
    return d;
}

// Single-MUFU tanh (MUFU.TANH, sm_75+). ~1e-4-class abs error; recurrence is
// contractive (leak 0.8) and output averages 2048 terms -> rel_err ~2e-4.
__device__ __forceinline__ float ftanh(float x) {
    float r; asm("tanh.approx.f32 %0, %1;" : "=f"(r) : "f"(x)); return r;
}
// Exact tanh for the one-time init path (keeps h0/r0 exact; cost irrelevant).
__device__ __forceinline__ float ftanh_exact(float x) {
    float e = __expf(2.0f * x);
    return fmaf(-2.0f, __frcp_rn(e + 1.0f), 1.0f);
}

// ---- shared proxy-parameter mixer (per hidden unit u, weight row `row`) ----
__device__ __forceinline__ float mix_unit(const float* __restrict__ w,
                                          const float* __restrict__ bias,
                                          int row, const float* gbv,
                                          float su0, float su1) {
    float a0 = bias ? bias[row * NSUP + 0] : 0.0f;
    float a1 = bias ? bias[row * NSUP + 1] : 0.0f;
    #pragma unroll
    for (int g = 0; g < GD; ++g) {
        a0 = fmaf(w[(row * NSUP + 0) * GD + g], gbv[g], a0);
        a1 = fmaf(w[(row * NSUP + 1) * GD + g], gbv[g], a1);
    }
    return a0 * su0 + a1 * su1;
}

// ================= kernel0: precompute wo (one-time, tiny) =================
__global__ void wo_kernel(const float* __restrict__ wo_w,
                          const float* __restrict__ gb,
                          const float* __restrict__ sup) {
    const int u = blockIdx.x * blockDim.x + threadIdx.x;
    if (u >= HID) return;
    float gbv[GD];
    #pragma unroll
    for (int g = 0; g < GD; ++g) gbv[g] = gb[(size_t)g * HID + u];
    const float su0 = sup[u], su1 = sup[HID + u];
    g_wo[u] = make_float2(mix_unit(wo_w, nullptr, 0, gbv, su0, su1),
                          mix_unit(wo_w, nullptr, 1, gbv, su0, su1));
}

// ================= kernel1: the recurrence (one CTA per batch) =============
__global__ void __launch_bounds__(TPB, 1)
rnn_kernel(const float* __restrict__ input,   // (B, T, I)
           const float* __restrict__ noise,   // (B, T, H)
           const float* __restrict__ wi_w,    // (I, S, G)
           const float* __restrict__ m_w,     // (R, S, G)
           const float* __restrict__ n_w,     // (R, S, G)
           const float* __restrict__ wi_b,    // (I, S)
           const float* __restrict__ m_b,     // (R, S)
           const float* __restrict__ n_b,     // (R, S)
           const float* __restrict__ h0_w,    // (S, G)
           const float* __restrict__ gb,      // (G, H)
           const float* __restrict__ sup)     // (S, H)
{
    __shared__ float4 s_in[SEQ];          // whole per-batch input, staged once (16 KB)
    __shared__ float2 s_part[2][NWARP];   // double-buffered warp partials -> 1 bar/step

    const int tid  = threadIdx.x;
    const int b    = blockIdx.x;
    const int wid  = tid >> 5;
    const int lane = tid & 31;

    // stage input[b] into shared
    const float4* in4 = reinterpret_cast<const float4*>(input) + (size_t)b * SEQ;
    for (int i = tid; i < SEQ; i += TPB) s_in[i] = in4[i];

    // ---------------- per-unit proxy parameters (registers) ----------------
    // Folds: wi' = ALPHA*wi, m' = ALPHA*m; leak 0.8 and noise 0.05 as immediates.
    float2 hreg[NPAIR], rreg[NPAIR];
    float2 n0v[NPAIR], n1v[NPAIR], m0v[NPAIR], m1v[NPAIR];
    float2 wiv[INPUT_SZ][NPAIR];

    const int ubase = tid * CPT;
    for (int j = 0; j < NPAIR; ++j) {
        for (int half = 0; half < 2; ++half) {
            const int u = ubase + 2 * j + half;
            float gbv[GD];
            #pragma unroll
            for (int g = 0; g < GD; ++g) gbv[g] = gb[(size_t)g * HID + u];
            const float su0 = sup[u];
            const float su1 = sup[HID + u];

            reinterpret_cast<float*>(&wiv[0][j])[half] = 0.2f * mix_unit(wi_w, wi_b, 0, gbv, su0, su1);
            reinterpret_cast<float*>(&wiv[1][j])[half] = 0.2f * mix_unit(wi_w, wi_b, 1, gbv, su0, su1);
            reinterpret_cast<float*>(&wiv[2][j])[half] = 0.2f * mix_unit(wi_w, wi_b, 2, gbv, su0, su1);
            reinterpret_cast<float*>(&wiv[3][j])[half] = 0.2f * mix_unit(wi_w, wi_b, 3, gbv, su0, su1);
            reinterpret_cast<float*>(&m0v[j])[half]  = 0.2f * mix_unit(m_w, m_b, 0, gbv, su0, su1);
            reinterpret_cast<float*>(&m1v[j])[half]  = 0.2f * mix_unit(m_w, m_b, 1, gbv, su0, su1);
            reinterpret_cast<float*>(&n0v[j])[half]  = mix_unit(n_w, n_b, 0, gbv, su0, su1);
            reinterpret_cast<float*>(&n1v[j])[half]  = mix_unit(n_w, n_b, 1, gbv, su0, su1);

            float a0 = 0.0f, a1 = 0.0f;
            #pragma unroll
            for (int g = 0; g < GD; ++g) {
                a0 = fmaf(h0_w[g],      gbv[g], a0);
                a1 = fmaf(h0_w[GD + g], gbv[g], a1);
            }
            const float h0u = a0 * su0 + a1 * su1;
            reinterpret_cast<float*>(&hreg[j])[half] = h0u;
            reinterpret_cast<float*>(&rreg[j])[half] = ftanh_exact(h0u);
        }
    }
    __syncthreads();  // s_in ready

    // ---------------- main recurrence ----------------
    // thread owns units [tid*4, tid*4+4) -> one float4 of noise / r per step
    const float4* nz4 = reinterpret_cast<const float4*>(noise)
                        + (size_t)b * SEQ * (HID / 4) + tid;
    float4* rout = g_r + (size_t)b * SEQ * (HID / 4) + tid;

    // distance-2 noise prefetch (streaming: read-once)
    float4 nA = __ldcs(&nz4[0]);
    float4 nB = __ldcs(&nz4[HID / 4]);

    const float2 K08  = make_float2(0.8f, 0.8f);
    const float2 K005 = make_float2(0.05f, 0.05f);

    auto step = [&](int t, float4& z) {
        // rank-2 dot on current r
        float2 a0 = make_float2(0.f, 0.f), a1 = a0;
        #pragma unroll
        for (int j = 0; j < NPAIR; ++j) {
            a0 = ffma2(rreg[j], n0v[j], a0);
            a1 = ffma2(rreg[j], n1v[j], a1);
        }
        float p0 = a0.x + a0.y, p1 = a1.x + a1.y;
        #pragma unroll
        for (int off = 16; off > 0; off >>= 1) {
            p0 += __shfl_xor_sync(0xffffffffu, p0, off);
            p1 += __shfl_xor_sync(0xffffffffu, p1, off);
        }
        const int buf = t & 1;
        if (lane == 0) s_part[buf][wid] = make_float2(p0, p1);

        // s-independent work overlapped with the reduce
        const float4 inv = s_in[t];
        const float2 ix = make_float2(inv.x, inv.x);
        const float2 iy = make_float2(inv.y, inv.y);
        const float2 iz = make_float2(inv.z, inv.z);
        const float2 iw = make_float2(inv.w, inv.w);
        float2 nzf[NPAIR];
        nzf[0] = make_float2(z.x, z.y);
        nzf[1] = make_float2(z.z, z.w);
        float2 tac[NPAIR];
        #pragma unroll
        for (int j = 0; j < NPAIR; ++j) {
            float2 tmp = fmul2(ix, wiv[0][j]);
            tmp = ffma2(iy, wiv[1][j], tmp);
            tmp = ffma2(iz, wiv[2][j], tmp);
            tmp = ffma2(iw, wiv[3][j], tmp);
            tmp = ffma2(K005, nzf[j], tmp);
            tmp = ffma2(K08, hreg[j], tmp);
            tac[j] = tmp;
        }
        // prefetch noise for t+2 (branchless clamp; unused at the tail)
        const int tn = min(t + 2, SEQ - 1);
        z = __ldcs(&nz4[(size_t)tn * (HID / 4)]);

        __syncthreads();
        // Cross-warp combine: pairs of lanes broadcast-load one of 16 partials,
        // then a 4-level butterfly within each 16-lane half -> sum in all lanes.
        const float2 q = s_part[buf][lane & (NWARP - 1)];
        float s0 = q.x, s1 = q.y;
        #pragma unroll
        for (int off = 8; off > 0; off >>= 1) {
            s0 += __shfl_xor_sync(0xffffffffu, s0, off);
            s1 += __shfl_xor_sync(0xffffffffu, s1, off);
        }

        const float2 s0v = make_float2(s0, s0);
        const float2 s1v = make_float2(s1, s1);
        #pragma unroll
        for (int j = 0; j < NPAIR; ++j) {
            const float2 hn = ffma2(s0v, m0v[j], ffma2(s1v, m1v[j], tac[j]));
            hreg[j] = hn;
            rreg[j].x = ftanh(hn.x);
            rreg[j].y = ftanh(hn.y);
        }
        // store r_t for the deferred output projection (fire-and-forget)
        rout[(size_t)t * (HID / 4)] =
            make_float4(rreg[0].x, rreg[0].y, rreg[1].x, rreg[1].y);
    };

    #pragma unroll 1
    for (int t = 0; t < SEQ; t += 2) {
        step(t,     nA);
        step(t + 1, nB);
    }
}

// ================= kernel2: deferred output projection =====================
// grid (BATCH, SEQ/8), block 256: warp w handles t = blockIdx.y*8 + w.
__global__ void __launch_bounds__(256, 4)
out_kernel(float* __restrict__ out) {
    const int b    = blockIdx.x;
    const int wid  = threadIdx.x >> 5;
    const int lane = threadIdx.x & 31;
    const int t    = blockIdx.y * 8 + wid;

    const float4* rr = g_r + ((size_t)b * SEQ + t) * (HID / 4);
    const float4* wv = reinterpret_cast<const float4*>(g_wo);

    float o0 = 0.f, o1 = 0.f;
    #pragma unroll
    for (int k = 0; k < 16; ++k) {
        const float4 rv = __ldcs(&rr[k * 32 + lane]);          // h = k*128 + lane*4
        const float4 wa = __ldg(&wv[k * 64 + lane * 2]);       // (wo0,wo1) for h, h+1
        const float4 wb = __ldg(&wv[k * 64 + lane * 2 + 1]);   // (wo0,wo1) for h+2, h+3
        o0 = fmaf(rv.x, wa.x, fmaf(rv.y, wa.z, fmaf(rv.z, wb.x, fmaf(rv.w, wb.z, o0))));
        o1 = fmaf(rv.x, wa.y, fmaf(rv.y, wa.w, fmaf(rv.z, wb.y, fmaf(rv.w, wb.w, o1))));
    }
    #pragma unroll
    for (int off = 16; off > 0; off >>= 1) {
        o0 += __shfl_xor_sync(0xffffffffu, o0, off);
        o1 += __shfl_xor_sync(0xffffffffu, o1, off);
    }
    if (lane == 0)
        reinterpret_cast<float2*>(out)[(size_t)b * SEQ + t] = make_float2(o0, o1);
}

extern "C" void kernel_launch(void* const* d_in, const int* in_sizes, int n_in,
                              void* d_out, int out_size) {
    (void)in_sizes; (void)n_in; (void)out_size;
    const float* input = (const float*)d_in[0];
    const float* noise = (const float*)d_in[1];
    const float* wi_w  = (const float*)d_in[2];
    const float* m_w   = (const float*)d_in[3];
    const float* n_w   = (const float*)d_in[4];
    const float* wo_w  = (const float*)d_in[5];
    const float* wi_b  = (const float*)d_in[6];
    const float* m_b   = (const float*)d_in[7];
    const float* n_b   = (const float*)d_in[8];
    const float* h0_w  = (const float*)d_in[9];
    const float* gb    = (const float*)d_in[10];
    const float* sup   = (const float*)d_in[11];

    wo_kernel<<<HID / 256, 256>>>(wo_w, gb, sup);
    rnn_kernel<<<BATCH, TPB>>>(input, noise, wi_w, m_w, n_w,
                               wi_b, m_b, n_b, h0_w, gb, sup);
    out_kernel<<<dim3(BATCH, SEQ / 8), 256>>>((float*)d_out);
}